// round 16
// baseline (speedup 1.0000x reference)
#include <cuda_runtime.h>
#include <math.h>
#include <stdint.h>

// ---------------- problem constants ----------------
#define BB   8
#define SSQ  1024
#define HIDD 1024
#define NH   8
#define HDD  128
#define MDD  8
#define NL   3
#define EPSS 1e-7f
#define INV_SQRT_D 0.08838834764831845f   // 1/sqrt(128)

// ---------------- scratch (device globals; no cudaMalloc allowed) ----------------
__device__ float g_cur   [BB * SSQ * HIDD];            // fp32 residual stream
__device__ float g_curt  [BB * SSQ * HIDD];            // tf32-rounded shadow of cur
__device__ float g_qkv   [BB * SSQ * 3 * HIDD];        // q,k get scaled+rounded in place
__device__ float g_scores[(size_t)BB * NH * SSQ * SSQ];
__device__ float g_o     [BB * SSQ * HIDD];
__device__ float g_wtq   [3 * HIDD * HIDD];            // W_qkv^T (rounded)
__device__ float g_wto   [HIDD * HIDD];                // W_out^T (rounded)
__device__ float g_vt    [BB * NH * HDD * SSQ];        // V^T per head [bh][d][s] (rounded)

// ---------------- helpers ----------------
__device__ __forceinline__ uint32_t f2tf(float x) {
    uint32_t u;
    asm("cvt.rna.tf32.f32 %0, %1;" : "=r"(u) : "f"(x));
    return u;
}
__device__ __forceinline__ float f2tff(float x) { return __uint_as_float(f2tf(x)); }

__device__ __forceinline__ void cpa16(uint32_t dst, const float* src) {
    asm volatile("cp.async.cg.shared.global [%0], [%1], 16;\n" :: "r"(dst), "l"(src));
}
__device__ __forceinline__ void cpa_commit(void) {
    asm volatile("cp.async.commit_group;\n");
}

#define LDSM4(d0, d1, d2, d3, addr)                                         \
    asm volatile("ldmatrix.sync.aligned.m8n8.x4.shared.b16 {%0,%1,%2,%3}, [%4];" \
                 : "=r"(d0), "=r"(d1), "=r"(d2), "=r"(d3) : "r"(addr))

#define MMA_TF32(acc, a0, a1, a2, a3, b0, b1)                               \
    asm volatile(                                                            \
        "mma.sync.aligned.m16n8k8.row.col.f32.tf32.tf32.f32 "               \
        "{%0,%1,%2,%3}, {%4,%5,%6,%7}, {%8,%9}, {%0,%1,%2,%3};\n"           \
        : "+f"((acc)[0]), "+f"((acc)[1]), "+f"((acc)[2]), "+f"((acc)[3])    \
        : "r"(a0), "r"(a1), "r"(a2), "r"(a3), "r"(b0), "r"(b1))

// copy x -> g_cur (exact) and g_curt (tf32-rounded)
__global__ void k_copy_round(const float4* __restrict__ src, float4* __restrict__ dst,
                             float4* __restrict__ dstr, int n4) {
    int i = blockIdx.x * blockDim.x + threadIdx.x;
    if (i >= n4) return;
    float4 v = src[i];
    dst[i] = v;
    float4 r = make_float4(f2tff(v.x), f2tff(v.y), f2tff(v.z), f2tff(v.w));
    dstr[i] = r;
}

// dst[n*K + k] = round(src[k*N + n])
__global__ void k_transpose(const float* __restrict__ src, float* __restrict__ dst, int K, int N) {
    __shared__ float t[32][33];
    int n0 = blockIdx.x * 32, k0 = blockIdx.y * 32;
    int tx = threadIdx.x, ty = threadIdx.y;
#pragma unroll
    for (int j = 0; j < 32; j += 8)
        t[ty + j][tx] = src[(size_t)(k0 + ty + j) * N + n0 + tx];
    __syncthreads();
#pragma unroll
    for (int j = 0; j < 32; j += 8)
        dst[(size_t)(n0 + ty + j) * K + k0 + tx] = f2tff(t[tx][ty + j]);
}

// g_vt[bh][d][s] = round(V[b,s,h,d])
__global__ void k_vt(void) {
    __shared__ float t[32][33];
    int z = blockIdx.z; int b = z >> 3, h = z & 7;
    int s0 = blockIdx.x * 32, d0 = blockIdx.y * 32;
    int tx = threadIdx.x, ty = threadIdx.y;
    const float* src = g_qkv + (size_t)b * SSQ * 3 * HIDD + 2 * HIDD + h * HDD;
#pragma unroll
    for (int j = 0; j < 32; j += 8)
        t[ty + j][tx] = src[(size_t)(s0 + ty + j) * (3 * HIDD) + d0 + tx];
    __syncthreads();
    float* dst = g_vt + (size_t)z * HDD * SSQ;
#pragma unroll
    for (int j = 0; j < 32; j += 8)
        dst[(size_t)(d0 + ty + j) * SSQ + s0 + tx] = f2tff(t[tx][ty + j]);
}

// ---------------- expmap0: scale + round q,k in place ----------------
__global__ void k_scales_apply(void) {
    int gw = (blockIdx.x * blockDim.x + threadIdx.x) >> 5;  // one warp per (b,h,s)
    int lane = threadIdx.x & 31;
    if (gw >= BB * NH * SSQ) return;
    int s = gw & (SSQ - 1);
    int bh = gw >> 10;
    int b = bh >> 3, h = bh & 7;
    float* q = g_qkv + (size_t)(b * SSQ + s) * (3 * HIDD) + h * HDD;
    float* k = q + HIDD;
    float qv[4], kv[4];
    float sq = 0.f, sk = 0.f;
#pragma unroll
    for (int j = 0; j < 4; j++) {
        int d = lane + 32 * j;
        qv[j] = q[d]; sq = fmaf(qv[j], qv[j], sq);
        kv[j] = k[d]; sk = fmaf(kv[j], kv[j], sk);
    }
#pragma unroll
    for (int o = 16; o; o >>= 1) {
        sq += __shfl_xor_sync(0xffffffffu, sq, o);
        sk += __shfl_xor_sync(0xffffffffu, sk, o);
    }
    float nq = fmaxf(sqrtf(sq), EPSS);
    float scq = tanhf(nq) / nq * INV_SQRT_D;
    float nk = fmaxf(sqrtf(sk), EPSS);
    float sck = tanhf(nk) / nk;
#pragma unroll
    for (int j = 0; j < 4; j++) {
        int d = lane + 32 * j;
        q[d] = f2tff(qv[j] * scq);
        k[d] = f2tff(kv[j] * sck);
    }
}

// ---------------- BK=16 tf32 GEMM (R11 variant; used for scores, K=128) ----------------
#define SROW 16
#define STG_WORDS (128 * SROW)
#define STG_BYTES (STG_WORDS * 4)

__device__ __forceinline__ void load_stage(
    uint32_t* as, uint32_t* bs,
    const float* A, const float* B, int lda, int ldb,
    int m0, int n0, int k0, int rr, int cs, int soff)
{
#pragma unroll
    for (int i = 0; i < 2; i++) {
        int row = rr + i * 64;
        cpa16((uint32_t)__cvta_generic_to_shared(as + (row << 4) + soff),
              A + (size_t)(m0 + row) * lda + k0 + cs * 4);
        cpa16((uint32_t)__cvta_generic_to_shared(bs + (row << 4) + soff),
              B + (size_t)(n0 + row) * ldb + k0 + cs * 4);
    }
    cpa_commit();
}

__global__ __launch_bounds__(256, 2) void k_mma(
    const float* __restrict__ Abase, long long sA1, long long sA2, int lda,
    const float* __restrict__ Bbase, long long sB1, long long sB2, int ldb,
    float*       __restrict__ Cbase, long long sC1, long long sC2, int ldc,
    const float* __restrict__ bias, int K)
{
    __shared__ uint32_t As[3][STG_WORDS];
    __shared__ uint32_t Bs[3][STG_WORDS];

    const int z = blockIdx.z;
    const long long zh = z >> 3, zl = z & 7;
    const float* A = Abase + zh * sA1 + zl * sA2;
    const float* B = Bbase + zh * sB1 + zl * sB2;
    float*       C = Cbase + zh * sC1 + zl * sC2;

    const int m0 = blockIdx.y * 128;
    const int n0 = blockIdx.x * 128;
    const int tid = threadIdx.x;
    const int w = tid >> 5, lane = tid & 31;
    const int wm = w & 1, wn = w >> 1;
    const int g = lane >> 2, tg = lane & 3;

    const int rr = tid >> 2;
    const int cs = tid & 3;
    const int soff = ((cs ^ ((rr >> 1) & 3)) << 2);

    const int lt = lane >> 3, lr = lane & 7;
    const uint32_t asB = (uint32_t)__cvta_generic_to_shared(&As[0][0]);
    const uint32_t bsB = (uint32_t)__cvta_generic_to_shared(&Bs[0][0]);
    uint32_t aAddr[4], bAddr[2];
#pragma unroll
    for (int mi = 0; mi < 4; mi++) {
        int r = wm * 64 + mi * 16 + (lt & 1) * 8 + lr;
        int csb = lt >> 1;
        aAddr[mi] = asB + (uint32_t)(r * 64 + ((csb ^ ((r >> 1) & 3)) << 4));
    }
#pragma unroll
    for (int p = 0; p < 2; p++) {
        int r = wn * 32 + p * 16 + (lt >> 1) * 8 + lr;
        int csb = lt & 1;
        bAddr[p] = bsB + (uint32_t)(r * 64 + ((csb ^ ((r >> 1) & 3)) << 4));
    }

    float acc[4][4][4];
#pragma unroll
    for (int mi = 0; mi < 4; mi++)
#pragma unroll
        for (int ni = 0; ni < 4; ni++)
#pragma unroll
            for (int r = 0; r < 4; r++) acc[mi][ni][r] = 0.f;

    const int nc = K >> 4;
    load_stage(As[0], Bs[0], A, B, lda, ldb, m0, n0, 0, rr, cs, soff);
    load_stage(As[1], Bs[1], A, B, lda, ldb, m0, n0, 16, rr, cs, soff);

    int st = 0;
    for (int c = 0; c < nc; c++) {
        if (c + 1 < nc) asm volatile("cp.async.wait_group 1;\n");
        else            asm volatile("cp.async.wait_group 0;\n");
        __syncthreads();

        const uint32_t sb = (uint32_t)st * STG_BYTES;

#pragma unroll
        for (int kh = 0; kh < 2; kh++) {
            const uint32_t kx = (uint32_t)(kh << 5);
            uint32_t af[4][4], bf[2][4];
#pragma unroll
            for (int mi = 0; mi < 4; mi++)
                LDSM4(af[mi][0], af[mi][1], af[mi][2], af[mi][3], (aAddr[mi] + sb) ^ kx);
#pragma unroll
            for (int p = 0; p < 2; p++)
                LDSM4(bf[p][0], bf[p][1], bf[p][2], bf[p][3], (bAddr[p] + sb) ^ kx);
#pragma unroll
            for (int mi = 0; mi < 4; mi++)
#pragma unroll
                for (int ni = 0; ni < 4; ni++) {
                    MMA_TF32(acc[mi][ni], af[mi][0], af[mi][1], af[mi][2], af[mi][3],
                             bf[ni >> 1][(ni & 1) * 2], bf[ni >> 1][(ni & 1) * 2 + 1]);
                }
        }
        if (c + 2 < nc) {
            int st2 = st + 2; if (st2 >= 3) st2 -= 3;
            load_stage(As[st2], Bs[st2], A, B, lda, ldb, m0, n0, (c + 2) * 16, rr, cs, soff);
        }
        if (++st == 3) st = 0;
    }

#pragma unroll
    for (int mi = 0; mi < 4; mi++) {
        int r0 = m0 + wm * 64 + mi * 16 + g;
#pragma unroll
        for (int ni = 0; ni < 4; ni++) {
            int c = n0 + wn * 32 + ni * 8 + 2 * tg;
            float b0 = 0.f, b1 = 0.f;
            if (bias) { b0 = bias[c]; b1 = bias[c + 1]; }
            float2 v;
            v.x = acc[mi][ni][0] + b0; v.y = acc[mi][ni][1] + b1;
            *(float2*)(C + (size_t)r0 * ldc + c) = v;
            v.x = acc[mi][ni][2] + b0; v.y = acc[mi][ni][3] + b1;
            *(float2*)(C + (size_t)(r0 + 8) * ldc + c) = v;
        }
    }
}

// ---------------- BK=32 tf32 GEMM (K=1024 shapes: QKV, AV, final) ----------------
// Same 128x128 / 8-warp / 3-stage / 1-barrier skeleton as k_mma, but BK=32:
// 64 MMAs per warp per barrier (2x amortization). 96 KB dynamic SMEM, 2 CTAs/SM.
// Rows: 32 floats = 8 x 16B chunks; swizzle phys = c ^ (r&7); kh hop = XOR(kh<<5).
#define STG32_BYTES 16384                       // per operand per stage
#define SMEM32_BYTES (3 * 2 * STG32_BYTES)      // 98304

extern __shared__ uint32_t dyn32[];

__global__ __launch_bounds__(256, 2) void k_mma32(
    const float* __restrict__ Abase, long long sA1, long long sA2, int lda,
    const float* __restrict__ Bbase, long long sB1, long long sB2, int ldb,
    float*       __restrict__ Cbase, long long sC1, long long sC2, int ldc,
    const float* __restrict__ bias, int K)
{
    uint32_t* As = dyn32;                        // 3 x 4096 words
    uint32_t* Bs = dyn32 + 3 * (STG32_BYTES / 4);

    const int z = blockIdx.z;
    const long long zh = z >> 3, zl = z & 7;
    const float* A = Abase + zh * sA1 + zl * sA2;
    const float* B = Bbase + zh * sB1 + zl * sB2;
    float*       C = Cbase + zh * sC1 + zl * sC2;

    const int m0 = blockIdx.y * 128;
    const int n0 = blockIdx.x * 128;
    const int tid = threadIdx.x;
    const int w = tid >> 5, lane = tid & 31;
    const int wm = w & 1, wn = w >> 1;
    const int g = lane >> 2, tg = lane & 3;
    const int lt = lane >> 3, lr = lane & 7;

    // staging: 128 rows x 8 chunks = 1024 chunks per operand; 4 per thread
    const int rs = tid >> 1;                    // row 0..127
    const int cb = (tid & 1) * 4;               // base chunk 0 or 4
    uint32_t soff[4];
#pragma unroll
    for (int i = 0; i < 4; i++)
        soff[i] = (uint32_t)(rs * 128 + (((cb + i) ^ (rs & 7)) << 4));
    const uint32_t asB = (uint32_t)__cvta_generic_to_shared(As);
    const uint32_t bsB = (uint32_t)__cvta_generic_to_shared(Bs);
    const float* gA = A + (size_t)(m0 + rs) * lda + cb * 4;
    const float* gB = B + (size_t)(n0 + rs) * ldb + cb * 4;

#define ISSUE32(stIdx, k0)                                                   \
    {                                                                        \
        uint32_t as_ = asB + (uint32_t)(stIdx) * STG32_BYTES;                \
        uint32_t bs_ = bsB + (uint32_t)(stIdx) * STG32_BYTES;                \
        cpa16(as_ + soff[0], gA + (k0));                                     \
        cpa16(as_ + soff[1], gA + (k0) + 4);                                 \
        cpa16(as_ + soff[2], gA + (k0) + 8);                                 \
        cpa16(as_ + soff[3], gA + (k0) + 12);                                \
        cpa16(bs_ + soff[0], gB + (k0));                                     \
        cpa16(bs_ + soff[1], gB + (k0) + 4);                                 \
        cpa16(bs_ + soff[2], gB + (k0) + 8);                                 \
        cpa16(bs_ + soff[3], gB + (k0) + 12);                                \
        cpa_commit();                                                        \
    }

    // LDSM lane addresses (kh=0; kh hop via XOR(kh<<5), kh = 0..3)
    uint32_t aAddr[4], bAddr[2];
#pragma unroll
    for (int mi = 0; mi < 4; mi++) {
        int r = wm * 64 + mi * 16 + (lt & 1) * 8 + lr;
        int sel = lt >> 1;
        aAddr[mi] = asB + (uint32_t)(r * 128 + ((sel ^ (r & 7)) << 4));
    }
#pragma unroll
    for (int p = 0; p < 2; p++) {
        int r = wn * 32 + p * 16 + (lt >> 1) * 8 + lr;
        int sel = lt & 1;
        bAddr[p] = bsB + (uint32_t)(r * 128 + ((sel ^ (r & 7)) << 4));
    }

    float acc[4][4][4];
#pragma unroll
    for (int mi = 0; mi < 4; mi++)
#pragma unroll
        for (int ni = 0; ni < 4; ni++)
#pragma unroll
            for (int r = 0; r < 4; r++) acc[mi][ni][r] = 0.f;

    const int nc = K >> 5;                      // K/32 chunks
    ISSUE32(0, 0);
    ISSUE32(1, 32);

    int st = 0;
    for (int c = 0; c < nc; c++) {
        if (c + 1 < nc) asm volatile("cp.async.wait_group 1;\n");
        else            asm volatile("cp.async.wait_group 0;\n");
        __syncthreads();

        const uint32_t sb = (uint32_t)st * STG32_BYTES;

#pragma unroll
        for (int kh = 0; kh < 4; kh++) {
            const uint32_t kx = (uint32_t)(kh << 5);
            uint32_t af[4][4], bf[2][4];
#pragma unroll
            for (int mi = 0; mi < 4; mi++)
                LDSM4(af[mi][0], af[mi][1], af[mi][2], af[mi][3], (aAddr[mi] + sb) ^ kx);
#pragma unroll
            for (int p = 0; p < 2; p++)
                LDSM4(bf[p][0], bf[p][1], bf[p][2], bf[p][3], (bAddr[p] + sb) ^ kx);
#pragma unroll
            for (int mi = 0; mi < 4; mi++)
#pragma unroll
                for (int ni = 0; ni < 4; ni++) {
                    MMA_TF32(acc[mi][ni], af[mi][0], af[mi][1], af[mi][2], af[mi][3],
                             bf[ni >> 1][(ni & 1) * 2], bf[ni >> 1][(ni & 1) * 2 + 1]);
                }
        }
        if (c + 2 < nc) {
            int st2 = st + 2; if (st2 >= 3) st2 -= 3;
            ISSUE32(st2, (c + 2) * 32);
        }
        if (++st == 3) st = 0;
    }
#undef ISSUE32

    // epilogue
#pragma unroll
    for (int mi = 0; mi < 4; mi++) {
        int r0 = m0 + wm * 64 + mi * 16 + g;
#pragma unroll
        for (int ni = 0; ni < 4; ni++) {
            int c = n0 + wn * 32 + ni * 8 + 2 * tg;
            float b0 = 0.f, b1 = 0.f;
            if (bias) { b0 = bias[c]; b1 = bias[c + 1]; }
            float2 v;
            v.x = acc[mi][ni][0] + b0; v.y = acc[mi][ni][1] + b1;
            *(float2*)(C + (size_t)r0 * ldc + c) = v;
            v.x = acc[mi][ni][2] + b0; v.y = acc[mi][ni][3] + b1;
            *(float2*)(C + (size_t)(r0 + 8) * ldc + c) = v;
        }
    }
}

// ---------------- row softmax over S=1024: warp per row, no barriers ----------------
__global__ __launch_bounds__(256) void k_softmax(void) {
    const int wid = threadIdx.x >> 5, lane = threadIdx.x & 31;
    const size_t row = (size_t)blockIdx.x * 8 + wid;
    float* p = g_scores + row * SSQ;

    float4 v[8];
    float mx = -1e30f;
#pragma unroll
    for (int j = 0; j < 8; j++) {
        v[j] = *(float4*)&p[(lane + j * 32) * 4];
        mx = fmaxf(mx, fmaxf(fmaxf(v[j].x, v[j].y), fmaxf(v[j].z, v[j].w)));
    }
#pragma unroll
    for (int o = 16; o; o >>= 1) mx = fmaxf(mx, __shfl_xor_sync(0xffffffffu, mx, o));

    float sum = 0.f;
#pragma unroll
    for (int j = 0; j < 8; j++) {
        v[j].x = __expf(v[j].x - mx); v[j].y = __expf(v[j].y - mx);
        v[j].z = __expf(v[j].z - mx); v[j].w = __expf(v[j].w - mx);
        sum += (v[j].x + v[j].y) + (v[j].z + v[j].w);
    }
#pragma unroll
    for (int o = 16; o; o >>= 1) sum += __shfl_xor_sync(0xffffffffu, sum, o);

    float inv = 1.f / sum;
#pragma unroll
    for (int j = 0; j < 8; j++) {
        float4 r;
        r.x = f2tff(v[j].x * inv); r.y = f2tff(v[j].y * inv);
        r.z = f2tff(v[j].z * inv); r.w = f2tff(v[j].w * inv);
        *(float4*)&p[(lane + j * 32) * 4] = r;
    }
}

// ---------------- manifold projection + residual update (also refresh rounded shadow) ----------------
__global__ __launch_bounds__(256) void k_manifold(
    const float* __restrict__ Wp, const float* __restrict__ bp,
    const float* __restrict__ Wa, const float* __restrict__ ba)
{
    __shared__ float sO[HIDD];
    __shared__ float sm[MDD];
    const int row = blockIdx.x;
    const int tid = threadIdx.x;

    *(float4*)&sO[tid * 4] = *(const float4*)&g_o[(size_t)row * HIDD + tid * 4];
    __syncthreads();

    const int wid = tid >> 5, lane = tid & 31;
    float part = 0.f;
    for (int i = lane; i < HIDD; i += 32) part = fmaf(sO[i], Wp[i * MDD + wid], part);
#pragma unroll
    for (int o = 16; o; o >>= 1) part += __shfl_xor_sync(0xffffffffu, part, o);
    if (lane == 0) sm[wid] = part + bp[wid];
    __syncthreads();

    const int c = tid * 4;
    float4 u = *(const float4*)&ba[c];
#pragma unroll
    for (int mi = 0; mi < MDD; mi++) {
        float mv = sm[mi];
        float4 w = *(const float4*)&Wa[mi * HIDD + c];
        u.x = fmaf(mv, w.x, u.x);
        u.y = fmaf(mv, w.y, u.y);
        u.z = fmaf(mv, w.z, u.z);
        u.w = fmaf(mv, w.w, u.w);
    }
    size_t off = (size_t)row * HIDD + c;
    float4 cv = *(float4*)&g_cur[off];
    cv.x += u.x; cv.y += u.y; cv.z += u.z; cv.w += u.w;
    *(float4*)&g_cur[off] = cv;
    float4 rv = make_float4(f2tff(cv.x), f2tff(cv.y), f2tff(cv.z), f2tff(cv.w));
    *(float4*)&g_curt[off] = rv;
}

// ---------------- launcher ----------------
extern "C" void kernel_launch(void* const* d_in, const int* in_sizes, int n_in,
                              void* d_out, int out_size) {
    (void)in_sizes; (void)n_in; (void)out_size;
    const float* x      = (const float*)d_in[0];
    const float* W_qkv  = (const float*)d_in[1];
    const float* b_qkv  = (const float*)d_in[2];
    const float* W_pinv = (const float*)d_in[3];
    const float* b_pinv = (const float*)d_in[4];
    const float* W_attn = (const float*)d_in[5];
    const float* b_attn = (const float*)d_in[6];
    const float* W_out  = (const float*)d_in[7];
    const float* b_out  = (const float*)d_in[8];
    float* out = (float*)d_out;

    float *p_cur, *p_curt, *p_qkv, *p_scores, *p_o, *p_wtq, *p_wto, *p_vt;
    cudaGetSymbolAddress((void**)&p_cur, g_cur);
    cudaGetSymbolAddress((void**)&p_curt, g_curt);
    cudaGetSymbolAddress((void**)&p_qkv, g_qkv);
    cudaGetSymbolAddress((void**)&p_scores, g_scores);
    cudaGetSymbolAddress((void**)&p_o, g_o);
    cudaGetSymbolAddress((void**)&p_wtq, g_wtq);
    cudaGetSymbolAddress((void**)&p_wto, g_wto);
    cudaGetSymbolAddress((void**)&p_vt, g_vt);

    cudaFuncSetAttribute(k_mma32, cudaFuncAttributeMaxDynamicSharedMemorySize, SMEM32_BYTES);

    // cur = x (exact + rounded shadow)
    {
        int n4 = BB * SSQ * HIDD / 4;
        k_copy_round<<<(n4 + 255) / 256, 256>>>((const float4*)x, (float4*)p_cur,
                                                (float4*)p_curt, n4);
    }
    // transpose + round weights (loop-invariant)
    k_transpose<<<dim3(3 * HIDD / 32, HIDD / 32), dim3(32, 8)>>>(W_qkv, p_wtq, HIDD, 3 * HIDD);
    k_transpose<<<dim3(HIDD / 32, HIDD / 32), dim3(32, 8)>>>(W_out, p_wto, HIDD, HIDD);

    const long long M1 = 1024 * 1024;  // SSQ*SSQ == SSQ*HIDD

    for (int l = 0; l < NL; l++) {
        // qkv = round(cur) @ round(W_qkv) + b_qkv   (M=8192, N=3072, K=1024)
        k_mma32<<<dim3(3 * HIDD / 128, BB * SSQ / 128, 1), 256, SMEM32_BYTES>>>(
            p_curt, 0, 0, HIDD,
            p_wtq,  0, 0, HIDD,
            p_qkv,  0, 0, 3 * HIDD,
            b_qkv, HIDD);

        // expmap0 scale + tf32 round of q,k in place
        k_scales_apply<<<BB * NH * SSQ * 32 / 256, 256>>>();

        // V^T per head (rounded)
        k_vt<<<dim3(SSQ / 32, HDD / 32, BB * NH), dim3(32, 8)>>>();

        // scores[bh] = qf @ kf^T   (M=N=1024, K=128, batched over 64 bh)
        k_mma<<<dim3(SSQ / 128, SSQ / 128, BB * NH), 256>>>(
            p_qkv,        (long long)SSQ * 3 * HIDD, HDD, 3 * HIDD,
            p_qkv + HIDD, (long long)SSQ * 3 * HIDD, HDD, 3 * HIDD,
            p_scores,     8 * M1, M1, SSQ,
            nullptr, HDD);

        // softmax rows (rounds P to tf32): warp per row, 8 rows/block
        k_softmax<<<BB * NH * SSQ / 8, 256>>>();

        // O[bh] = P @ V   (M=1024, N=128, K=1024)
        k_mma32<<<dim3(HDD / 128, SSQ / 128, BB * NH), 256, SMEM32_BYTES>>>(
            p_scores, 8 * M1, M1, SSQ,
            p_vt,     8LL * HDD * SSQ, (long long)HDD * SSQ, SSQ,
            p_o,      M1, HDD, HIDD,
            nullptr, SSQ);

        // manifold projection + residual (+ refresh rounded shadow)
        k_manifold<<<BB * SSQ, 256>>>(W_pinv, b_pinv,
                                      W_attn + (size_t)l * MDD * HIDD,
                                      b_attn + (size_t)l * HIDD);
    }

    // out = round(cur) @ round(W_out) + b_out   (M=8192, N=1024, K=1024)
    k_mma32<<<dim3(HIDD / 128, BB * SSQ / 128, 1), 256, SMEM32_BYTES>>>(
        p_curt, 0, 0, HIDD,
        p_wto,  0, 0, HIDD,
        out,    0, 0, HIDD,
        b_out, HIDD);
}

// round 17
// speedup vs baseline: 1.1207x; 1.1207x over previous
#include <cuda_runtime.h>
#include <math.h>
#include <stdint.h>

// ---------------- problem constants ----------------
#define BB   8
#define SSQ  1024
#define HIDD 1024
#define NH   8
#define HDD  128
#define MDD  8
#define NL   3
#define EPSS 1e-7f
#define INV_SQRT_D 0.08838834764831845f   // 1/sqrt(128)

// ---------------- scratch (device globals; no cudaMalloc allowed) ----------------
__device__ float g_cur   [BB * SSQ * HIDD];            // fp32 residual stream
__device__ float g_curt  [BB * SSQ * HIDD];            // tf32-rounded shadow of cur
__device__ float g_qkv   [BB * SSQ * 3 * HIDD];        // q,k stored scaled+rounded by epilogue
__device__ float g_scores[(size_t)BB * NH * SSQ * SSQ];
__device__ float g_o     [BB * SSQ * HIDD];
__device__ float g_wtq   [3 * HIDD * HIDD];            // W_qkv^T (rounded)
__device__ float g_wto   [HIDD * HIDD];                // W_out^T (rounded)
__device__ float g_vt    [BB * NH * HDD * SSQ];        // V^T per head [bh][d][s] (rounded)

// ---------------- helpers ----------------
__device__ __forceinline__ uint32_t f2tf(float x) {
    uint32_t u;
    asm("cvt.rna.tf32.f32 %0, %1;" : "=r"(u) : "f"(x));
    return u;
}
__device__ __forceinline__ float f2tff(float x) { return __uint_as_float(f2tf(x)); }

__device__ __forceinline__ void cpa16(uint32_t dst, const float* src) {
    asm volatile("cp.async.cg.shared.global [%0], [%1], 16;\n" :: "r"(dst), "l"(src));
}
__device__ __forceinline__ void cpa_commit(void) {
    asm volatile("cp.async.commit_group;\n");
}

#define LDSM4(d0, d1, d2, d3, addr)                                         \
    asm volatile("ldmatrix.sync.aligned.m8n8.x4.shared.b16 {%0,%1,%2,%3}, [%4];" \
                 : "=r"(d0), "=r"(d1), "=r"(d2), "=r"(d3) : "r"(addr))

#define MMA_TF32(acc, a0, a1, a2, a3, b0, b1)                               \
    asm volatile(                                                            \
        "mma.sync.aligned.m16n8k8.row.col.f32.tf32.tf32.f32 "               \
        "{%0,%1,%2,%3}, {%4,%5,%6,%7}, {%8,%9}, {%0,%1,%2,%3};\n"           \
        : "+f"((acc)[0]), "+f"((acc)[1]), "+f"((acc)[2]), "+f"((acc)[3])    \
        : "r"(a0), "r"(a1), "r"(a2), "r"(a3), "r"(b0), "r"(b1))

// copy x -> g_cur (exact) and g_curt (tf32-rounded)
__global__ void k_copy_round(const float4* __restrict__ src, float4* __restrict__ dst,
                             float4* __restrict__ dstr, int n4) {
    int i = blockIdx.x * blockDim.x + threadIdx.x;
    if (i >= n4) return;
    float4 v = src[i];
    dst[i] = v;
    float4 r = make_float4(f2tff(v.x), f2tff(v.y), f2tff(v.z), f2tff(v.w));
    dstr[i] = r;
}

// dst[n*K + k] = round(src[k*N + n])
__global__ void k_transpose(const float* __restrict__ src, float* __restrict__ dst, int K, int N) {
    __shared__ float t[32][33];
    int n0 = blockIdx.x * 32, k0 = blockIdx.y * 32;
    int tx = threadIdx.x, ty = threadIdx.y;
#pragma unroll
    for (int j = 0; j < 32; j += 8)
        t[ty + j][tx] = src[(size_t)(k0 + ty + j) * N + n0 + tx];
    __syncthreads();
#pragma unroll
    for (int j = 0; j < 32; j += 8)
        dst[(size_t)(n0 + ty + j) * K + k0 + tx] = f2tff(t[tx][ty + j]);
}

// g_vt[bh][d][s] = round(V[b,s,h,d])
__global__ void k_vt(void) {
    __shared__ float t[32][33];
    int z = blockIdx.z; int b = z >> 3, h = z & 7;
    int s0 = blockIdx.x * 32, d0 = blockIdx.y * 32;
    int tx = threadIdx.x, ty = threadIdx.y;
    const float* src = g_qkv + (size_t)b * SSQ * 3 * HIDD + 2 * HIDD + h * HDD;
#pragma unroll
    for (int j = 0; j < 32; j += 8)
        t[ty + j][tx] = src[(size_t)(s0 + ty + j) * (3 * HIDD) + d0 + tx];
    __syncthreads();
    float* dst = g_vt + (size_t)z * HDD * SSQ;
#pragma unroll
    for (int j = 0; j < 32; j += 8)
        dst[(size_t)(d0 + ty + j) * SSQ + s0 + tx] = f2tff(t[tx][ty + j]);
}

// ---------------- BK=16 tf32 GEMM (R11 skeleton; all GEMM families) ----------------
// Block 128x128, 256 threads (8 warps: 2m x 4n). 3-stage cp.async pipeline, late
// prefetch, ONE __syncthreads per chunk. XOR swizzle, LDSM fragments.
// qk_fuse: for QKV launch only — tiles with blockIdx.x<16 (q,k heads; N-tile ==
// head_dim) compute the expmap0 row norm in-CTA and store scaled+rounded values.
#define SROW 16
#define STG_WORDS (128 * SROW)
#define STG_BYTES (STG_WORDS * 4)

__device__ __forceinline__ void load_stage(
    uint32_t* as, uint32_t* bs,
    const float* A, const float* B, int lda, int ldb,
    int m0, int n0, int k0, int rr, int cs, int soff)
{
#pragma unroll
    for (int i = 0; i < 2; i++) {
        int row = rr + i * 64;
        cpa16((uint32_t)__cvta_generic_to_shared(as + (row << 4) + soff),
              A + (size_t)(m0 + row) * lda + k0 + cs * 4);
        cpa16((uint32_t)__cvta_generic_to_shared(bs + (row << 4) + soff),
              B + (size_t)(n0 + row) * ldb + k0 + cs * 4);
    }
    cpa_commit();
}

__global__ __launch_bounds__(256, 2) void k_mma(
    const float* __restrict__ Abase, long long sA1, long long sA2, int lda,
    const float* __restrict__ Bbase, long long sB1, long long sB2, int ldb,
    float*       __restrict__ Cbase, long long sC1, long long sC2, int ldc,
    const float* __restrict__ bias, int K, int qk_fuse)
{
    __shared__ uint32_t As[3][STG_WORDS];
    __shared__ uint32_t Bs[3][STG_WORDS];

    const int z = blockIdx.z;
    const long long zh = z >> 3, zl = z & 7;
    const float* A = Abase + zh * sA1 + zl * sA2;
    const float* B = Bbase + zh * sB1 + zl * sB2;
    float*       C = Cbase + zh * sC1 + zl * sC2;

    const int m0 = blockIdx.y * 128;
    const int n0 = blockIdx.x * 128;
    const int tid = threadIdx.x;
    const int w = tid >> 5, lane = tid & 31;
    const int wm = w & 1, wn = w >> 1;
    const int g = lane >> 2, tg = lane & 3;

    const int rr = tid >> 2;
    const int cs = tid & 3;
    const int soff = ((cs ^ ((rr >> 1) & 3)) << 2);

    const int lt = lane >> 3, lr = lane & 7;
    const uint32_t asB = (uint32_t)__cvta_generic_to_shared(&As[0][0]);
    const uint32_t bsB = (uint32_t)__cvta_generic_to_shared(&Bs[0][0]);
    uint32_t aAddr[4], bAddr[2];
#pragma unroll
    for (int mi = 0; mi < 4; mi++) {
        int r = wm * 64 + mi * 16 + (lt & 1) * 8 + lr;
        int csb = lt >> 1;
        aAddr[mi] = asB + (uint32_t)(r * 64 + ((csb ^ ((r >> 1) & 3)) << 4));
    }
#pragma unroll
    for (int p = 0; p < 2; p++) {
        int r = wn * 32 + p * 16 + (lt >> 1) * 8 + lr;
        int csb = lt & 1;
        bAddr[p] = bsB + (uint32_t)(r * 64 + ((csb ^ ((r >> 1) & 3)) << 4));
    }

    float acc[4][4][4];
#pragma unroll
    for (int mi = 0; mi < 4; mi++)
#pragma unroll
        for (int ni = 0; ni < 4; ni++)
#pragma unroll
            for (int r = 0; r < 4; r++) acc[mi][ni][r] = 0.f;

    const int nc = K >> 4;
    load_stage(As[0], Bs[0], A, B, lda, ldb, m0, n0, 0, rr, cs, soff);
    load_stage(As[1], Bs[1], A, B, lda, ldb, m0, n0, 16, rr, cs, soff);

    int st = 0;
    for (int c = 0; c < nc; c++) {
        if (c + 1 < nc) asm volatile("cp.async.wait_group 1;\n");
        else            asm volatile("cp.async.wait_group 0;\n");
        __syncthreads();

        const uint32_t sb = (uint32_t)st * STG_BYTES;

#pragma unroll
        for (int kh = 0; kh < 2; kh++) {
            const uint32_t kx = (uint32_t)(kh << 5);
            uint32_t af[4][4], bf[2][4];
#pragma unroll
            for (int mi = 0; mi < 4; mi++)
                LDSM4(af[mi][0], af[mi][1], af[mi][2], af[mi][3], (aAddr[mi] + sb) ^ kx);
#pragma unroll
            for (int p = 0; p < 2; p++)
                LDSM4(bf[p][0], bf[p][1], bf[p][2], bf[p][3], (bAddr[p] + sb) ^ kx);
#pragma unroll
            for (int mi = 0; mi < 4; mi++)
#pragma unroll
                for (int ni = 0; ni < 4; ni++) {
                    MMA_TF32(acc[mi][ni], af[mi][0], af[mi][1], af[mi][2], af[mi][3],
                             bf[ni >> 1][(ni & 1) * 2], bf[ni >> 1][(ni & 1) * 2 + 1]);
                }
        }
        if (c + 2 < nc) {
            int st2 = st + 2; if (st2 >= 3) st2 -= 3;
            load_stage(As[st2], Bs[st2], A, B, lda, ldb, m0, n0, (c + 2) * 16, rr, cs, soff);
        }
        if (++st == 3) st = 0;
    }

    // ---- add bias into acc (common to both epilogues) ----
#pragma unroll
    for (int ni = 0; ni < 4; ni++) {
        int c = n0 + wn * 32 + ni * 8 + 2 * tg;
        float b0 = 0.f, b1 = 0.f;
        if (bias) { b0 = bias[c]; b1 = bias[c + 1]; }
#pragma unroll
        for (int mi = 0; mi < 4; mi++) {
            acc[mi][ni][0] += b0; acc[mi][ni][1] += b1;
            acc[mi][ni][2] += b0; acc[mi][ni][3] += b1;
        }
    }

    if (qk_fuse && blockIdx.x < 16) {
        // ---- fused expmap0: row norm over this CTA's 128-col head segment ----
        float rs0[4], rs1[4];
#pragma unroll
        for (int mi = 0; mi < 4; mi++) {
            float a0 = 0.f, a1 = 0.f;
#pragma unroll
            for (int ni = 0; ni < 4; ni++) {
                a0 = fmaf(acc[mi][ni][0], acc[mi][ni][0], a0);
                a0 = fmaf(acc[mi][ni][1], acc[mi][ni][1], a0);
                a1 = fmaf(acc[mi][ni][2], acc[mi][ni][2], a1);
                a1 = fmaf(acc[mi][ni][3], acc[mi][ni][3], a1);
            }
            // reduce over the tg quad (lanes g*4 .. g*4+3)
            a0 += __shfl_xor_sync(0xffffffffu, a0, 1);
            a0 += __shfl_xor_sync(0xffffffffu, a0, 2);
            a1 += __shfl_xor_sync(0xffffffffu, a1, 1);
            a1 += __shfl_xor_sync(0xffffffffu, a1, 2);
            rs0[mi] = a0; rs1[mi] = a1;
        }
        __syncthreads();                 // As/Bs dead; reuse As as scratch
        float* rpart = (float*)&As[0][0];   // [4][128]
        if (tg == 0) {
#pragma unroll
            for (int mi = 0; mi < 4; mi++) {
                int r = wm * 64 + mi * 16 + g;
                rpart[wn * 128 + r]     = rs0[mi];
                rpart[wn * 128 + r + 8] = rs1[mi];
            }
        }
        __syncthreads();
        const float qmul = (blockIdx.x < 8) ? INV_SQRT_D : 1.0f;
#pragma unroll
        for (int mi = 0; mi < 4; mi++) {
            int r = wm * 64 + mi * 16 + g;
            float n2a = rpart[r] + rpart[128 + r] + rpart[256 + r] + rpart[384 + r];
            float n2b = rpart[r + 8] + rpart[128 + r + 8] + rpart[256 + r + 8] + rpart[384 + r + 8];
            float na = fmaxf(sqrtf(n2a), EPSS);
            float nb = fmaxf(sqrtf(n2b), EPSS);
            float sa = tanhf(na) / na * qmul;
            float sb2 = tanhf(nb) / nb * qmul;
            int r0 = m0 + r;
#pragma unroll
            for (int ni = 0; ni < 4; ni++) {
                int c = n0 + wn * 32 + ni * 8 + 2 * tg;
                float2 v;
                v.x = f2tff(acc[mi][ni][0] * sa); v.y = f2tff(acc[mi][ni][1] * sa);
                *(float2*)(C + (size_t)r0 * ldc + c) = v;
                v.x = f2tff(acc[mi][ni][2] * sb2); v.y = f2tff(acc[mi][ni][3] * sb2);
                *(float2*)(C + (size_t)(r0 + 8) * ldc + c) = v;
            }
        }
    } else {
        // ---- plain epilogue ----
#pragma unroll
        for (int mi = 0; mi < 4; mi++) {
            int r0 = m0 + wm * 64 + mi * 16 + g;
#pragma unroll
            for (int ni = 0; ni < 4; ni++) {
                int c = n0 + wn * 32 + ni * 8 + 2 * tg;
                float2 v;
                v.x = acc[mi][ni][0]; v.y = acc[mi][ni][1];
                *(float2*)(C + (size_t)r0 * ldc + c) = v;
                v.x = acc[mi][ni][2]; v.y = acc[mi][ni][3];
                *(float2*)(C + (size_t)(r0 + 8) * ldc + c) = v;
            }
        }
    }
}

// ---------------- row softmax over S=1024: warp per row, no barriers ----------------
__global__ __launch_bounds__(256) void k_softmax(void) {
    const int wid = threadIdx.x >> 5, lane = threadIdx.x & 31;
    const size_t row = (size_t)blockIdx.x * 8 + wid;
    float* p = g_scores + row * SSQ;

    float4 v[8];
    float mx = -1e30f;
#pragma unroll
    for (int j = 0; j < 8; j++) {
        v[j] = *(float4*)&p[(lane + j * 32) * 4];
        mx = fmaxf(mx, fmaxf(fmaxf(v[j].x, v[j].y), fmaxf(v[j].z, v[j].w)));
    }
#pragma unroll
    for (int o = 16; o; o >>= 1) mx = fmaxf(mx, __shfl_xor_sync(0xffffffffu, mx, o));

    float sum = 0.f;
#pragma unroll
    for (int j = 0; j < 8; j++) {
        v[j].x = __expf(v[j].x - mx); v[j].y = __expf(v[j].y - mx);
        v[j].z = __expf(v[j].z - mx); v[j].w = __expf(v[j].w - mx);
        sum += (v[j].x + v[j].y) + (v[j].z + v[j].w);
    }
#pragma unroll
    for (int o = 16; o; o >>= 1) sum += __shfl_xor_sync(0xffffffffu, sum, o);

    float inv = 1.f / sum;
#pragma unroll
    for (int j = 0; j < 8; j++) {
        float4 r;
        r.x = f2tff(v[j].x * inv); r.y = f2tff(v[j].y * inv);
        r.z = f2tff(v[j].z * inv); r.w = f2tff(v[j].w * inv);
        *(float4*)&p[(lane + j * 32) * 4] = r;
    }
}

// ---------------- manifold projection + residual update (also refresh rounded shadow) ----------------
__global__ __launch_bounds__(256) void k_manifold(
    const float* __restrict__ Wp, const float* __restrict__ bp,
    const float* __restrict__ Wa, const float* __restrict__ ba)
{
    __shared__ float sO[HIDD];
    __shared__ float sm[MDD];
    const int row = blockIdx.x;
    const int tid = threadIdx.x;

    *(float4*)&sO[tid * 4] = *(const float4*)&g_o[(size_t)row * HIDD + tid * 4];
    __syncthreads();

    const int wid = tid >> 5, lane = tid & 31;
    float part = 0.f;
    for (int i = lane; i < HIDD; i += 32) part = fmaf(sO[i], Wp[i * MDD + wid], part);
#pragma unroll
    for (int o = 16; o; o >>= 1) part += __shfl_xor_sync(0xffffffffu, part, o);
    if (lane == 0) sm[wid] = part + bp[wid];
    __syncthreads();

    const int c = tid * 4;
    float4 u = *(const float4*)&ba[c];
#pragma unroll
    for (int mi = 0; mi < MDD; mi++) {
        float mv = sm[mi];
        float4 w = *(const float4*)&Wa[mi * HIDD + c];
        u.x = fmaf(mv, w.x, u.x);
        u.y = fmaf(mv, w.y, u.y);
        u.z = fmaf(mv, w.z, u.z);
        u.w = fmaf(mv, w.w, u.w);
    }
    size_t off = (size_t)row * HIDD + c;
    float4 cv = *(float4*)&g_cur[off];
    cv.x += u.x; cv.y += u.y; cv.z += u.z; cv.w += u.w;
    *(float4*)&g_cur[off] = cv;
    float4 rv = make_float4(f2tff(cv.x), f2tff(cv.y), f2tff(cv.z), f2tff(cv.w));
    *(float4*)&g_curt[off] = rv;
}

// ---------------- launcher ----------------
extern "C" void kernel_launch(void* const* d_in, const int* in_sizes, int n_in,
                              void* d_out, int out_size) {
    (void)in_sizes; (void)n_in; (void)out_size;
    const float* x      = (const float*)d_in[0];
    const float* W_qkv  = (const float*)d_in[1];
    const float* b_qkv  = (const float*)d_in[2];
    const float* W_pinv = (const float*)d_in[3];
    const float* b_pinv = (const float*)d_in[4];
    const float* W_attn = (const float*)d_in[5];
    const float* b_attn = (const float*)d_in[6];
    const float* W_out  = (const float*)d_in[7];
    const float* b_out  = (const float*)d_in[8];
    float* out = (float*)d_out;

    float *p_cur, *p_curt, *p_qkv, *p_scores, *p_o, *p_wtq, *p_wto, *p_vt;
    cudaGetSymbolAddress((void**)&p_cur, g_cur);
    cudaGetSymbolAddress((void**)&p_curt, g_curt);
    cudaGetSymbolAddress((void**)&p_qkv, g_qkv);
    cudaGetSymbolAddress((void**)&p_scores, g_scores);
    cudaGetSymbolAddress((void**)&p_o, g_o);
    cudaGetSymbolAddress((void**)&p_wtq, g_wtq);
    cudaGetSymbolAddress((void**)&p_wto, g_wto);
    cudaGetSymbolAddress((void**)&p_vt, g_vt);

    // cur = x (exact + rounded shadow)
    {
        int n4 = BB * SSQ * HIDD / 4;
        k_copy_round<<<(n4 + 255) / 256, 256>>>((const float4*)x, (float4*)p_cur,
                                                (float4*)p_curt, n4);
    }
    // transpose + round weights (loop-invariant)
    k_transpose<<<dim3(3 * HIDD / 32, HIDD / 32), dim3(32, 8)>>>(W_qkv, p_wtq, HIDD, 3 * HIDD);
    k_transpose<<<dim3(HIDD / 32, HIDD / 32), dim3(32, 8)>>>(W_out, p_wto, HIDD, HIDD);

    const long long M1 = 1024 * 1024;  // SSQ*SSQ == SSQ*HIDD

    for (int l = 0; l < NL; l++) {
        // qkv = round(cur) @ round(W_qkv) + b_qkv, with fused expmap0 scale+round
        // on q,k tiles (blockIdx.x < 16)   (M=8192, N=3072, K=1024)
        k_mma<<<dim3(3 * HIDD / 128, BB * SSQ / 128, 1), 256>>>(
            p_curt, 0, 0, HIDD,
            p_wtq,  0, 0, HIDD,
            p_qkv,  0, 0, 3 * HIDD,
            b_qkv, HIDD, 1);

        // V^T per head (rounded)
        k_vt<<<dim3(SSQ / 32, HDD / 32, BB * NH), dim3(32, 8)>>>();

        // scores[bh] = qf @ kf^T   (M=N=1024, K=128, batched over 64 bh)
        k_mma<<<dim3(SSQ / 128, SSQ / 128, BB * NH), 256>>>(
            p_qkv,        (long long)SSQ * 3 * HIDD, HDD, 3 * HIDD,
            p_qkv + HIDD, (long long)SSQ * 3 * HIDD, HDD, 3 * HIDD,
            p_scores,     8 * M1, M1, SSQ,
            nullptr, HDD, 0);

        // softmax rows (rounds P to tf32): warp per row, 8 rows/block
        k_softmax<<<BB * NH * SSQ / 8, 256>>>();

        // O[bh] = P @ V   (M=1024, N=128, K=1024)
        k_mma<<<dim3(HDD / 128, SSQ / 128, BB * NH), 256>>>(
            p_scores, 8 * M1, M1, SSQ,
            p_vt,     8LL * HDD * SSQ, (long long)HDD * SSQ, SSQ,
            p_o,      M1, HDD, HIDD,
            nullptr, SSQ, 0);

        // manifold projection + residual (+ refresh rounded shadow)
        k_manifold<<<BB * SSQ, 256>>>(W_pinv, b_pinv,
                                      W_attn + (size_t)l * MDD * HIDD,
                                      b_attn + (size_t)l * HIDD);
    }

    // out = round(cur) @ round(W_out) + b_out   (M=8192, N=1024, K=1024)
    k_mma<<<dim3(HIDD / 128, BB * SSQ / 128, 1), 256>>>(
        p_curt, 0, 0, HIDD,
        p_wto,  0, 0, HIDD,
        out,    0, 0, HIDD,
        b_out, HIDD, 0);
}